// round 14
// baseline (speedup 1.0000x reference)
#include <cuda_runtime.h>
#include <cuda_bf16.h>
#include <cuda_fp16.h>
#include <cstdint>

#define DI __device__ __forceinline__
#define FULLMASK 0xFFFFFFFFu

// ===================== problem dims =====================
#define NBATCH 4
#define NPIX   4096
#define NCH    1792
#define NCENT  4096
#define M_TOT  (NBATCH*NPIX)
#define NNEI   200
#define SCORE_ELEMS (NBATCH*NNEI*NPIX)
#define DCENTER 1792.0f

// ===================== scratch =====================
// split-bf16 transposed pooled inputs: x' = [xh | xl | xh], row-major [b*HW+p][3C]
__device__ __nv_bfloat16 g_xp0[(size_t)4*4096*768];
__device__ __nv_bfloat16 g_xp1[(size_t)4*1024*1536];
__device__ __nv_bfloat16 g_xp2[(size_t)4*256*3072];
// split-bf16 weights: w' = [wh | wh | wl], row-major [oc][3C]
__device__ __nv_bfloat16 g_wp1[(size_t)256*768];
__device__ __nv_bfloat16 g_wp2[(size_t)512*1536];
__device__ __nv_bfloat16 g_wp3[(size_t)1024*3072];
__device__ float g_conv0[4u*256*64*64];
__device__ float g_conv1[4u*512*32*32];
__device__ float g_conv2[4u*1024*16*16];
__device__ __nv_bfloat16 g_phi[(size_t)M_TOT*NCH];
__device__ __nv_bfloat16 g_ct [(size_t)NCENT*NCH];
__device__ float g_feats[M_TOT];
__device__ float g_cents[NCENT];
__device__ __half g_dist2h[(size_t)M_TOT*NCENT];

// ===================== PTX helpers (sm_100 baseline ISA) =====================
DI uint32_t smem_u32(const void* p) {
    uint32_t a;
    asm("{ .reg .u64 t; cvta.to.shared.u64 t, %1; cvt.u32.u64 %0, t; }" : "=r"(a) : "l"(p));
    return a;
}
DI void ldsm4(uint32_t* r, uint32_t a) {
    asm volatile("ldmatrix.sync.aligned.m8n8.x4.shared.b16 {%0,%1,%2,%3}, [%4];"
        : "=r"(r[0]), "=r"(r[1]), "=r"(r[2]), "=r"(r[3]) : "r"(a));
}
DI void mma16816(float* c, const uint32_t* a, uint32_t b0, uint32_t b1) {
    asm volatile("mma.sync.aligned.m16n8k16.row.col.f32.bf16.bf16.f32 "
        "{%0,%1,%2,%3}, {%4,%5,%6,%7}, {%8,%9}, {%0,%1,%2,%3};"
        : "+f"(c[0]), "+f"(c[1]), "+f"(c[2]), "+f"(c[3])
        : "r"(a[0]), "r"(a[1]), "r"(a[2]), "r"(a[3]), "r"(b0), "r"(b1));
}
DI void cpasync16(uint32_t dst, const void* src) {
    asm volatile("cp.async.cg.shared.global [%0], [%1], 16;" :: "r"(dst), "l"(src) : "memory");
}
DI void cp_commit() { asm volatile("cp.async.commit_group;" ::: "memory"); }
DI void cp_wait1()  { asm volatile("cp.async.wait_group 1;" ::: "memory"); }
DI void cp_wait0()  { asm volatile("cp.async.wait_group 0;" ::: "memory"); }

// ===================== launch 1: prep mega-kernel =====================
DI float pool_val(const float* __restrict__ plane, int H, int W, int p) {
    int w = p % W, h = p / W;
    float s = 0.f;
    #pragma unroll
    for (int dy = -1; dy <= 1; dy++) {
        int hh = h + dy;
        if (hh < 0 || hh >= H) continue;
        #pragma unroll
        for (int dx = -1; dx <= 1; dx++) {
            int ww = w + dx;
            if (ww < 0 || ww >= W) continue;
            s += plane[hh * W + ww];
        }
    }
    return s * (1.0f / 9.0f);
}

DI void poolT_body(const float* __restrict__ x, __nv_bfloat16* __restrict__ xp,
                   int C, int H, int W, int b, int ct, int ht,
                   float (*tile)[33], int t) {
    int c0 = ct * 32, hw0 = ht * 32;
    int HW = H * W, K3 = 3 * C;
    int tx = t & 31, ty = t >> 5;
    for (int i = ty; i < 32; i += 8) {
        int c = c0 + i;
        tile[i][tx] = pool_val(x + (size_t)(b * C + c) * HW, H, W, hw0 + tx);
    }
    __syncthreads();
    for (int i = ty; i < 32; i += 8) {
        int p = hw0 + i;
        float v = tile[tx][i];
        __nv_bfloat16 hi = __float2bfloat16(v);
        __nv_bfloat16 lo = __float2bfloat16(v - __bfloat162float(hi));
        size_t rb = (size_t)(b * HW + p) * K3;
        xp[rb + c0 + tx] = hi;
        xp[rb + C + c0 + tx] = lo;
        xp[rb + 2 * C + c0 + tx] = hi;
    }
    __syncthreads();
}

__global__ __launch_bounds__(256) void prep_kernel(
    const float* __restrict__ p0, const float* __restrict__ p1,
    const float* __restrict__ p2, const float* __restrict__ C,
    const float* __restrict__ w1, const float* __restrict__ w2,
    const float* __restrict__ w3) {
    __shared__ float tile[32][33];
    int bb = blockIdx.x, t = threadIdx.x;
    if (bb < 7168) {
        if (bb < 4096) {
            int b = bb >> 10, rem = bb & 1023;
            poolT_body(p0, g_xp0, 256, 64, 64, b, rem >> 7, rem & 127, tile, t);
        } else if (bb < 6144) {
            int v = bb - 4096;
            int b = v >> 9, rem = v & 511;
            poolT_body(p1, g_xp1, 512, 32, 32, b, rem >> 5, rem & 31, tile, t);
        } else {
            int v = bb - 6144;
            int b = v >> 8, rem = v & 255;
            poolT_body(p2, g_xp2, 1024, 16, 16, b, rem >> 3, rem & 7, tile, t);
        }
    } else if (bb < 14336) {
        int id = bb - 7168;
        int j0 = (id & 127) * 32, k0 = (id >> 7) * 32;
        int tx = t & 31, ty = t >> 5;
        for (int i = ty; i < 32; i += 8)
            tile[i][tx] = C[(size_t)(k0 + i) * 4096 + j0 + tx];
        __syncthreads();
        for (int i = ty; i < 32; i += 8)
            g_ct[(size_t)(j0 + i) * NCH + k0 + tx] = __float2bfloat16(tile[tx][i]);
    } else if (bb < 14464) {
        __shared__ float red[256];
        int id = bb - 14336;
        int j = (id & 127) * 32 + (t & 31);
        int kp = t >> 5;
        float s = 0.f;
        int kbeg = kp * 224, kend = kbeg + 224;
        for (int k = kbeg; k < kend; k++) {
            float v = C[(size_t)k * 4096 + j];
            s += v * v;
        }
        red[t] = s;
        __syncthreads();
        if (t < 32) {
            float acc = red[t];
            #pragma unroll
            for (int i = 1; i < 8; i++) acc += red[t + i * 32];
            g_cents[j] = acc;
        }
    } else {
        int id = bb - 14464;
        const float* wsrc; __nv_bfloat16* wdst; int Cc, oc;
        if (id < 256)      { wsrc = w1; wdst = g_wp1; Cc = 256;  oc = id; }
        else if (id < 768) { wsrc = w2; wdst = g_wp2; Cc = 512;  oc = id - 256; }
        else               { wsrc = w3; wdst = g_wp3; Cc = 1024; oc = id - 768; }
        int K3 = 3 * Cc, Cp2 = Cc + 2;
        for (int c = t; c < Cc; c += 256) {
            float v = wsrc[(size_t)oc * Cp2 + c];
            __nv_bfloat16 hi = __float2bfloat16(v);
            __nv_bfloat16 lo = __float2bfloat16(v - __bfloat162float(hi));
            wdst[(size_t)oc * K3 + c] = hi;
            wdst[(size_t)oc * K3 + Cc + c] = hi;
            wdst[(size_t)oc * K3 + 2 * Cc + c] = lo;
        }
    }
}

// w'/x' pairing: w' = [wh|wh|wl], x' = [xh|xl|xh] => dot = wh.xh + wh.xl + wl.xh

// ===================== shared GEMM tile machinery (compile-time K stride) =====================
#define A_STRIDE 144
#define SA_BYTES (128*144)
#define STAGE_BYTES (2*SA_BYTES)
#define NSTAGE 3
#define GEMM_SMEM (NSTAGE*STAGE_BYTES)    // 110592

template<int KST>
DI void tile_load_chunk(uint32_t sbuf, const __nv_bfloat16* __restrict__ aptr,
                        const __nv_bfloat16* __restrict__ bptr, int k0, int t) {
    uint32_t sA = sbuf, sB = sbuf + SA_BYTES;
    #pragma unroll
    for (int i = 0; i < 4; i++) {
        int idx = t + i * 256;
        int row = idx >> 3, seg = idx & 7;
        cpasync16(sA + row * A_STRIDE + seg * 16, aptr + (size_t)row * KST + k0 + seg * 8);
    }
    #pragma unroll
    for (int i = 0; i < 4; i++) {
        int idx = t + i * 256;
        int row = idx >> 3, seg = idx & 7;
        cpasync16(sB + row * A_STRIDE + seg * 16, bptr + (size_t)row * KST + k0 + seg * 8);
    }
    cp_commit();
}

template<int KST>
DI void tile_mainloop(uint32_t sbase, const __nv_bfloat16* aptr, const __nv_bfloat16* bptr,
                      int t, uint32_t a_base, uint32_t b_base, float c[4][4][4]) {
    constexpr int nchunk = KST / 64;
    tile_load_chunk<KST>(sbase, aptr, bptr, 0, t);
    tile_load_chunk<KST>(sbase + STAGE_BYTES, aptr, bptr, 64, t);
    int stage = 0;
    #pragma unroll 1
    for (int ck = 0; ck < nchunk; ck++) {
        if (ck == nchunk - 1) cp_wait0(); else cp_wait1();
        __syncthreads();
        if (ck + 2 < nchunk) {
            int ls = stage + 2; if (ls >= NSTAGE) ls -= NSTAGE;
            tile_load_chunk<KST>(sbase + ls * STAGE_BYTES, aptr, bptr, (ck + 2) * 64, t);
        }
        uint32_t sA = sbase + stage * STAGE_BYTES;
        uint32_t sB = sA + SA_BYTES;
        #pragma unroll
        for (int ks = 0; ks < 4; ks++) {
            uint32_t a[4][4];
            #pragma unroll
            for (int mi = 0; mi < 4; mi++)
                ldsm4(a[mi], sA + a_base + mi * (16 * A_STRIDE) + ks * 32);
            uint32_t bfr[2][4];
            #pragma unroll
            for (int np = 0; np < 2; np++)
                ldsm4(bfr[np], sB + b_base + np * (16 * A_STRIDE) + ks * 32);
            #pragma unroll
            for (int mi = 0; mi < 4; mi++)
                #pragma unroll
                for (int np = 0; np < 2; np++) {
                    mma16816(c[mi][np * 2 + 0], a[mi], bfr[np][0], bfr[np][1]);
                    mma16816(c[mi][np * 2 + 1], a[mi], bfr[np][2], bfr[np][3]);
                }
        }
        if (++stage >= NSTAGE) stage = 0;
    }
}

// ===================== launch 2: conv via split-bf16 tensor GEMM =====================
template<int CC, int WD>
DI void conv_tile(uint32_t sbase, const __nv_bfloat16* wp, const __nv_bfloat16* xp,
                  float* o, const float* wsrc, const float* bsrc,
                  int OC, int HW, int b, int oc0, int pp0, int t) {
    constexpr int K3 = 3 * CC;
    int lane = t & 31, wid = t >> 5;
    int wm = wid & 1, wn = wid >> 1;
    float c[4][4][4];
    #pragma unroll
    for (int i = 0; i < 4; i++)
        #pragma unroll
        for (int j = 0; j < 4; j++)
            #pragma unroll
            for (int r = 0; r < 4; r++) c[i][j][r] = 0.f;
    const uint32_t a_row = wm * 64 + (lane & 15);
    const uint32_t a_base = a_row * A_STRIDE + ((lane >> 4) * 16);
    const uint32_t b_row = wn * 32 + ((lane >> 4) * 8) + (lane & 7);
    const uint32_t b_base = b_row * A_STRIDE + (((lane >> 3) & 1) * 16);

    tile_mainloop<K3>(sbase, wp + (size_t)oc0 * K3, xp + (size_t)(b * HW + pp0) * K3,
                      t, a_base, b_base, c);

    constexpr int Cp2 = CC + 2;
    float invW = 2.f / (float)(WD - 1);
    #pragma unroll
    for (int mi = 0; mi < 4; mi++) {
        int r0 = oc0 + wm * 64 + mi * 16 + (lane >> 2);
        int r1 = r0 + 8;
        float cx0 = wsrc[(size_t)r0 * Cp2 + CC], cy0 = wsrc[(size_t)r0 * Cp2 + CC + 1], bb0 = bsrc[r0];
        float cx1 = wsrc[(size_t)r1 * Cp2 + CC], cy1 = wsrc[(size_t)r1 * Cp2 + CC + 1], bb1 = bsrc[r1];
        #pragma unroll
        for (int ni = 0; ni < 4; ni++) {
            int cc = pp0 + wn * 32 + ni * 8 + (lane & 3) * 2;
            float xga = -1.f + (float)(cc % WD) * invW, yga = -1.f + (float)(cc / WD) * invW;
            float xgb = -1.f + (float)((cc + 1) % WD) * invW, ygb = -1.f + (float)((cc + 1) / WD) * invW;
            float2 v0 = { c[mi][ni][0] + cx0 * xga + cy0 * yga + bb0,
                          c[mi][ni][1] + cx0 * xgb + cy0 * ygb + bb0 };
            float2 v1 = { c[mi][ni][2] + cx1 * xga + cy1 * yga + bb1,
                          c[mi][ni][3] + cx1 * xgb + cy1 * ygb + bb1 };
            *reinterpret_cast<float2*>(&o[(size_t)(b * OC + r0) * HW + cc]) = v0;
            *reinterpret_cast<float2*>(&o[(size_t)(b * OC + r1) * HW + cc]) = v1;
        }
    }
}

// grid 448: [0,64) L2 | [64,192) L1 | [192,448) L0
__global__ __launch_bounds__(256, 2) void convmma_kernel(
    const float* __restrict__ w1, const float* __restrict__ b1,
    const float* __restrict__ w2, const float* __restrict__ b2,
    const float* __restrict__ w3, const float* __restrict__ b3) {
    extern __shared__ __align__(16) char smem[];
    const uint32_t sbase = smem_u32(smem);
    int id = blockIdx.x, t = threadIdx.x;
    if (id < 64) {
        int b = id >> 4, rem = id & 15;
        conv_tile<1024, 16>(sbase, g_wp3, g_xp2, g_conv2, w3, b3,
                            1024, 256, b, (rem >> 1) * 128, (rem & 1) * 128, t);
    } else if (id < 192) {
        int v = id - 64;
        int b = v >> 5, rem = v & 31;
        conv_tile<512, 32>(sbase, g_wp2, g_xp1, g_conv1, w2, b2,
                           512, 1024, b, (rem >> 3) * 128, (rem & 7) * 128, t);
    } else {
        int v = id - 192;
        int b = v >> 6, rem = v & 63;
        conv_tile<256, 64>(sbase, g_wp1, g_xp0, g_conv0, w1, b1,
                           256, 4096, b, (rem >> 5) * 128, (rem & 31) * 128, t);
    }
}

// ===================== launch 3: phi (fused resize + out2 + feats) =====================
DI float bilin(const float* __restrict__ sp, int S, int p) {
    int h = p >> 6, ww = p & 63;
    float sc = (float)S / 64.f;
    float fy = ((float)h + 0.5f) * sc - 0.5f; fy = fminf(fmaxf(fy, 0.f), (float)(S - 1));
    float fx = ((float)ww + 0.5f) * sc - 0.5f; fx = fminf(fmaxf(fx, 0.f), (float)(S - 1));
    int y0 = (int)fy, x0 = (int)fx;
    int y1 = min(y0 + 1, S - 1), x1 = min(x0 + 1, S - 1);
    float wy = fy - (float)y0, wx = fx - (float)x0;
    float v00 = sp[y0 * S + x0], v01 = sp[y0 * S + x1];
    float v10 = sp[y1 * S + x0], v11 = sp[y1 * S + x1];
    return (1.f - wy) * ((1.f - wx) * v00 + wx * v01) + wy * ((1.f - wx) * v10 + wx * v11);
}

DI float fetch2(int b, int ch, int p) {
    if (ch < 256)  return g_conv0[(((size_t)(b * 256 + ch)) << 12) + p];
    if (ch < 768)  return bilin(&g_conv1[(size_t)(b * 512 + ch - 256) * 1024], 32, p);
    return bilin(&g_conv2[(size_t)(b * 1024 + ch - 768) * 256], 16, p);
}

__global__ __launch_bounds__(256) void phi_all_kernel(float* __restrict__ out2) {
    __shared__ float tile[32][33];
    __shared__ float fsmem[32];
    int b = blockIdx.y, p0 = blockIdx.x * 32;
    int tx = threadIdx.x & 31, ty = threadIdx.x >> 5;
    if (threadIdx.x < 32) fsmem[threadIdx.x] = 0.f;
    __syncthreads();
    #pragma unroll 1
    for (int ch0 = 0; ch0 < NCH; ch0 += 32) {
        for (int i = ty; i < 32; i += 8) {
            int ch = ch0 + i, p = p0 + tx;
            float v = fetch2(b, ch, p);
            tile[i][tx] = v;
            if (ch < 896)
                out2[(((size_t)(b * 896 + ch)) << 12) + p] = v;
        }
        __syncthreads();
        for (int i = ty; i < 32; i += 8) {
            int p = p0 + i;
            float v = tile[tx][i];
            g_phi[(size_t)(b * 4096 + p) * NCH + ch0 + tx] = __float2bfloat16(v);
            float s = v * v;
            s += __shfl_xor_sync(FULLMASK, s, 16);
            s += __shfl_xor_sync(FULLMASK, s, 8);
            s += __shfl_xor_sync(FULLMASK, s, 4);
            s += __shfl_xor_sync(FULLMASK, s, 2);
            s += __shfl_xor_sync(FULLMASK, s, 1);
            if (tx == 0) fsmem[i] += s;
        }
        __syncthreads();
    }
    if (threadIdx.x < 32)
        g_feats[b * 4096 + p0 + threadIdx.x] = fsmem[threadIdx.x];
}

// ===================== launch 4: distance GEMM (KST=1792 compile-time) =====================
__global__ __launch_bounds__(256, 2) void gemm_kernel() {
    extern __shared__ __align__(16) char smem[];
    const uint32_t sbase = smem_u32(smem);
    int t = threadIdx.x, lane = t & 31, wid = t >> 5;
    int wm = wid & 1, wn = wid >> 1;
    int m0 = blockIdx.x * 128, n0 = blockIdx.y * 128;

    float c[4][4][4];
    #pragma unroll
    for (int i = 0; i < 4; i++)
        #pragma unroll
        for (int j = 0; j < 4; j++)
            #pragma unroll
            for (int r = 0; r < 4; r++) c[i][j][r] = 0.f;

    const uint32_t a_row = wm * 64 + (lane & 15);
    const uint32_t a_base = a_row * A_STRIDE + ((lane >> 4) * 16);
    const uint32_t b_row = wn * 32 + ((lane >> 4) * 8) + (lane & 7);
    const uint32_t b_base = b_row * A_STRIDE + (((lane >> 3) & 1) * 16);

    tile_mainloop<NCH>(sbase, &g_phi[(size_t)m0 * NCH], &g_ct[(size_t)n0 * NCH],
                       t, a_base, b_base, c);

    #pragma unroll
    for (int mi = 0; mi < 4; mi++) {
        int r0 = m0 + wm * 64 + mi * 16 + (lane >> 2);
        float f0 = g_feats[r0] - DCENTER, f1 = g_feats[r0 + 8] - DCENTER;
        #pragma unroll
        for (int ni = 0; ni < 4; ni++) {
            int cc = n0 + wn * 32 + ni * 8 + (lane & 3) * 2;
            float ce0 = g_cents[cc], ce1 = g_cents[cc + 1];
            __half* dp = &g_dist2h[(size_t)r0 * 4096 + cc];
            __half2 h0 = __floats2half2_rn(f0 + ce0 - 2.f * c[mi][ni][0],
                                           f0 + ce1 - 2.f * c[mi][ni][1]);
            __half2 h1 = __floats2half2_rn(f1 + ce0 - 2.f * c[mi][ni][2],
                                           f1 + ce1 - 2.f * c[mi][ni][3]);
            *reinterpret_cast<__half2*>(dp) = h0;
            *reinterpret_cast<__half2*>(dp + (size_t)8 * 4096) = h1;
        }
    }
}

// ===================== launch 5: top-200 per row (16-bit keys, 2 radix passes) =====================
DI unsigned order16(unsigned h) {
    return (h & 0x8000u) ? ((~h) & 0xFFFFu) : (h | 0x8000u);
}

__global__ __launch_bounds__(256) void topk_kernel(float* __restrict__ out) {
    __shared__ unsigned hist[256];
    __shared__ unsigned scan[256];
    __shared__ unsigned sh_want, sh_prefix;
    __shared__ unsigned cnt_lt;
    __shared__ int sel[256];

    int row = blockIdx.x;
    int t = threadIdx.x;
    int lane = t & 31;

    unsigned keys[16];
    const uint4* src = reinterpret_cast<const uint4*>(&g_dist2h[(size_t)row * 4096]);
    #pragma unroll
    for (int j = 0; j < 2; j++) {
        uint4 v = src[t + j * 256];
        unsigned ws[4] = { v.x, v.y, v.z, v.w };
        #pragma unroll
        for (int q = 0; q < 4; q++) {
            keys[j * 8 + q * 2 + 0] = order16(ws[q] & 0xFFFFu);
            keys[j * 8 + q * 2 + 1] = order16(ws[q] >> 16);
        }
    }
    if (t == 0) { sh_want = NNEI; sh_prefix = 0; cnt_lt = 0; }
    __syncthreads();

    // pass 0: high byte (clustered) -> warp-aggregated atomics
    {
        hist[t] = 0;
        __syncthreads();
        #pragma unroll
        for (int j = 0; j < 16; j++) {
            unsigned d = keys[j] >> 8;
            unsigned m = __match_any_sync(FULLMASK, d);
            if ((m & ((1u << lane) - 1u)) == 0)
                atomicAdd(&hist[d], (unsigned)__popc(m));
        }
        __syncthreads();
        if (t < 32) {
            unsigned vals[8], tot = 0;
            #pragma unroll
            for (int i = 0; i < 8; i++) { vals[i] = hist[t * 8 + i]; tot += vals[i]; }
            unsigned run = tot;
            #pragma unroll
            for (int off = 1; off < 32; off <<= 1) {
                unsigned x = __shfl_up_sync(FULLMASK, run, off);
                if (t >= off) run += x;
            }
            unsigned acc = run - tot;
            #pragma unroll
            for (int i = 0; i < 8; i++) { acc += vals[i]; scan[t * 8 + i] = acc; }
        }
        __syncthreads();
        unsigned below = (t == 0) ? 0u : scan[t - 1];
        if (below < NNEI && NNEI <= scan[t]) {
            sh_want = NNEI - below;
            sh_prefix = (unsigned)t;
        }
        __syncthreads();
    }

    // pass 1: low byte, plain atomics
    {
        unsigned pfx = sh_prefix;
        unsigned want = sh_want;
        hist[t] = 0;
        __syncthreads();
        #pragma unroll
        for (int j = 0; j < 16; j++) {
            unsigned u = keys[j];
            if ((u >> 8) == pfx)
                atomicAdd(&hist[u & 255u], 1u);
        }
        __syncthreads();
        if (t < 32) {
            unsigned vals[8], tot = 0;
            #pragma unroll
            for (int i = 0; i < 8; i++) { vals[i] = hist[t * 8 + i]; tot += vals[i]; }
            unsigned run = tot;
            #pragma unroll
            for (int off = 1; off < 32; off <<= 1) {
                unsigned x = __shfl_up_sync(FULLMASK, run, off);
                if (t >= off) run += x;
            }
            unsigned acc = run - tot;
            #pragma unroll
            for (int i = 0; i < 8; i++) { acc += vals[i]; scan[t * 8 + i] = acc; }
        }
        __syncthreads();
        unsigned below = (t == 0) ? 0u : scan[t - 1];
        if (below < want && want <= scan[t]) {
            sh_prefix = (pfx << 8) | (unsigned)t;
        }
        __syncthreads();
    }

    unsigned T = sh_prefix;
    #pragma unroll
    for (int j = 0; j < 16; j++) {
        bool pr = keys[j] < T;
        unsigned m = __ballot_sync(FULLMASK, pr);
        if (m) {
            unsigned pos0 = 0;
            if (lane == 0) pos0 = atomicAdd(&cnt_lt, (unsigned)__popc(m));
            pos0 = __shfl_sync(FULLMASK, pos0, 0);
            if (pr) sel[pos0 + __popc(m & ((1u << lane) - 1u))] = (int)keys[j];
        }
    }
    __syncthreads();
    unsigned base = cnt_lt;
    if ((unsigned)t >= base) sel[t] = (t < NNEI) ? (int)T : 0x7FFFFFFF;
    __syncthreads();

    for (int k = 2; k <= 256; k <<= 1) {
        for (int j = k >> 1; j > 0; j >>= 1) {
            int ixj = t ^ j;
            if (ixj > t) {
                bool up = ((t & k) == 0);
                int a = sel[t], bv = sel[ixj];
                if ((a > bv) == up) { sel[t] = bv; sel[ixj] = a; }
            }
            __syncthreads();
        }
    }

    if (t < NNEI) {
        unsigned u = (unsigned)sel[t];
        unsigned h = (u & 0x8000u) ? (u & 0x7FFFu) : ((~u) & 0xFFFFu);
        float f = __half2float(__ushort_as_half((unsigned short)h)) + DCENTER;
        int b = row >> 12, p = row & 4095;
        out[(((size_t)(b * NNEI + t)) << 12) + p] = sqrtf(f);
    }
}

// ===================== host launcher =====================
extern "C" void kernel_launch(void* const* d_in, const int* in_sizes, int n_in,
                              void* d_out, int out_size) {
    const float* p0 = (const float*)d_in[0];
    const float* p1 = (const float*)d_in[1];
    const float* p2 = (const float*)d_in[2];
    const float* w1 = (const float*)d_in[5];
    const float* b1 = (const float*)d_in[6];
    const float* w2 = (const float*)d_in[7];
    const float* b2 = (const float*)d_in[8];
    const float* w3 = (const float*)d_in[9];
    const float* b3 = (const float*)d_in[10];
    const float* Cm = (const float*)d_in[11];
    float* score = (float*)d_out;
    float* out2  = score + SCORE_ELEMS;

    static bool attr_set = false;
    if (!attr_set) {
        cudaFuncSetAttribute(gemm_kernel, cudaFuncAttributeMaxDynamicSharedMemorySize, GEMM_SMEM);
        cudaFuncSetAttribute(convmma_kernel, cudaFuncAttributeMaxDynamicSharedMemorySize, GEMM_SMEM);
        attr_set = true;
    }

    prep_kernel<<<16256, 256>>>(p0, p1, p2, Cm, w1, w2, w3);
    convmma_kernel<<<448, 256, GEMM_SMEM>>>(w1, b1, w2, b2, w3, b3);
    phi_all_kernel<<<dim3(128, 4), 256>>>(out2);
    gemm_kernel<<<dim3(M_TOT/128, NCENT/128), 256, GEMM_SMEM>>>();
    topk_kernel<<<M_TOT, 256>>>(score);
}

// round 15
// speedup vs baseline: 1.0349x; 1.0349x over previous
#include <cuda_runtime.h>
#include <cuda_bf16.h>
#include <cuda_fp16.h>
#include <cstdint>

#define DI __device__ __forceinline__
#define FULLMASK 0xFFFFFFFFu

// ===================== problem dims =====================
#define NBATCH 4
#define NPIX   4096
#define NCH    1792
#define NCENT  4096
#define M_TOT  (NBATCH*NPIX)
#define NNEI   200
#define SCORE_ELEMS (NBATCH*NNEI*NPIX)
#define DCENTER 1792.0f

// ===================== scratch =====================
// split-bf16 transposed pooled inputs: x' = [xh | xl | xh], row-major [b*HW+p][3C]
__device__ __nv_bfloat16 g_xp0[(size_t)4*4096*768];
__device__ __nv_bfloat16 g_xp1[(size_t)4*1024*1536];
__device__ __nv_bfloat16 g_xp2[(size_t)4*256*3072];
// split-bf16 weights: w' = [wh | wh | wl], row-major [oc][3C]
__device__ __nv_bfloat16 g_wp1[(size_t)256*768];
__device__ __nv_bfloat16 g_wp2[(size_t)512*1536];
__device__ __nv_bfloat16 g_wp3[(size_t)1024*3072];
__device__ float g_conv0[4u*256*64*64];
__device__ float g_conv1[4u*512*32*32];
__device__ float g_conv2[4u*1024*16*16];
__device__ __nv_bfloat16 g_phi[(size_t)M_TOT*NCH];
__device__ __nv_bfloat16 g_ct [(size_t)NCENT*NCH];
__device__ float g_feats[M_TOT];
__device__ float g_cents[NCENT];
__device__ __half g_dist2h[(size_t)M_TOT*NCENT];

// ===================== PTX helpers (sm_100 baseline ISA) =====================
DI uint32_t smem_u32(const void* p) {
    uint32_t a;
    asm("{ .reg .u64 t; cvta.to.shared.u64 t, %1; cvt.u32.u64 %0, t; }" : "=r"(a) : "l"(p));
    return a;
}
DI void ldsm4(uint32_t* r, uint32_t a) {
    asm volatile("ldmatrix.sync.aligned.m8n8.x4.shared.b16 {%0,%1,%2,%3}, [%4];"
        : "=r"(r[0]), "=r"(r[1]), "=r"(r[2]), "=r"(r[3]) : "r"(a));
}
DI void mma16816(float* c, const uint32_t* a, uint32_t b0, uint32_t b1) {
    asm volatile("mma.sync.aligned.m16n8k16.row.col.f32.bf16.bf16.f32 "
        "{%0,%1,%2,%3}, {%4,%5,%6,%7}, {%8,%9}, {%0,%1,%2,%3};"
        : "+f"(c[0]), "+f"(c[1]), "+f"(c[2]), "+f"(c[3])
        : "r"(a[0]), "r"(a[1]), "r"(a[2]), "r"(a[3]), "r"(b0), "r"(b1));
}
DI void cpasync16(uint32_t dst, const void* src) {
    asm volatile("cp.async.cg.shared.global [%0], [%1], 16;" :: "r"(dst), "l"(src) : "memory");
}
DI void cp_commit() { asm volatile("cp.async.commit_group;" ::: "memory"); }
DI void cp_wait1()  { asm volatile("cp.async.wait_group 1;" ::: "memory"); }
DI void cp_wait0()  { asm volatile("cp.async.wait_group 0;" ::: "memory"); }

// ===================== launch 1: prep mega-kernel =====================
DI float pool_val(const float* __restrict__ plane, int H, int W, int p) {
    int w = p % W, h = p / W;
    float s = 0.f;
    #pragma unroll
    for (int dy = -1; dy <= 1; dy++) {
        int hh = h + dy;
        if (hh < 0 || hh >= H) continue;
        #pragma unroll
        for (int dx = -1; dx <= 1; dx++) {
            int ww = w + dx;
            if (ww < 0 || ww >= W) continue;
            s += plane[hh * W + ww];
        }
    }
    return s * (1.0f / 9.0f);
}

DI void poolT_body(const float* __restrict__ x, __nv_bfloat16* __restrict__ xp,
                   int C, int H, int W, int b, int ct, int ht,
                   float (*tile)[33], int t) {
    int c0 = ct * 32, hw0 = ht * 32;
    int HW = H * W, K3 = 3 * C;
    int tx = t & 31, ty = t >> 5;
    for (int i = ty; i < 32; i += 8) {
        int c = c0 + i;
        tile[i][tx] = pool_val(x + (size_t)(b * C + c) * HW, H, W, hw0 + tx);
    }
    __syncthreads();
    for (int i = ty; i < 32; i += 8) {
        int p = hw0 + i;
        float v = tile[tx][i];
        __nv_bfloat16 hi = __float2bfloat16(v);
        __nv_bfloat16 lo = __float2bfloat16(v - __bfloat162float(hi));
        size_t rb = (size_t)(b * HW + p) * K3;
        xp[rb + c0 + tx] = hi;
        xp[rb + C + c0 + tx] = lo;
        xp[rb + 2 * C + c0 + tx] = hi;
    }
    __syncthreads();
}

__global__ __launch_bounds__(256) void prep_kernel(
    const float* __restrict__ p0, const float* __restrict__ p1,
    const float* __restrict__ p2, const float* __restrict__ C,
    const float* __restrict__ w1, const float* __restrict__ w2,
    const float* __restrict__ w3) {
    __shared__ float tile[32][33];
    int bb = blockIdx.x, t = threadIdx.x;
    if (bb < 7168) {
        if (bb < 4096) {
            int b = bb >> 10, rem = bb & 1023;
            poolT_body(p0, g_xp0, 256, 64, 64, b, rem >> 7, rem & 127, tile, t);
        } else if (bb < 6144) {
            int v = bb - 4096;
            int b = v >> 9, rem = v & 511;
            poolT_body(p1, g_xp1, 512, 32, 32, b, rem >> 5, rem & 31, tile, t);
        } else {
            int v = bb - 6144;
            int b = v >> 8, rem = v & 255;
            poolT_body(p2, g_xp2, 1024, 16, 16, b, rem >> 3, rem & 7, tile, t);
        }
    } else if (bb < 14336) {
        int id = bb - 7168;
        int j0 = (id & 127) * 32, k0 = (id >> 7) * 32;
        int tx = t & 31, ty = t >> 5;
        for (int i = ty; i < 32; i += 8)
            tile[i][tx] = C[(size_t)(k0 + i) * 4096 + j0 + tx];
        __syncthreads();
        for (int i = ty; i < 32; i += 8)
            g_ct[(size_t)(j0 + i) * NCH + k0 + tx] = __float2bfloat16(tile[tx][i]);
    } else if (bb < 14464) {
        __shared__ float red[256];
        int id = bb - 14336;
        int j = (id & 127) * 32 + (t & 31);
        int kp = t >> 5;
        float s = 0.f;
        int kbeg = kp * 224, kend = kbeg + 224;
        for (int k = kbeg; k < kend; k++) {
            float v = C[(size_t)k * 4096 + j];
            s += v * v;
        }
        red[t] = s;
        __syncthreads();
        if (t < 32) {
            float acc = red[t];
            #pragma unroll
            for (int i = 1; i < 8; i++) acc += red[t + i * 32];
            g_cents[j] = acc;
        }
    } else {
        int id = bb - 14464;
        const float* wsrc; __nv_bfloat16* wdst; int Cc, oc;
        if (id < 256)      { wsrc = w1; wdst = g_wp1; Cc = 256;  oc = id; }
        else if (id < 768) { wsrc = w2; wdst = g_wp2; Cc = 512;  oc = id - 256; }
        else               { wsrc = w3; wdst = g_wp3; Cc = 1024; oc = id - 768; }
        int K3 = 3 * Cc, Cp2 = Cc + 2;
        for (int c = t; c < Cc; c += 256) {
            float v = wsrc[(size_t)oc * Cp2 + c];
            __nv_bfloat16 hi = __float2bfloat16(v);
            __nv_bfloat16 lo = __float2bfloat16(v - __bfloat162float(hi));
            wdst[(size_t)oc * K3 + c] = hi;
            wdst[(size_t)oc * K3 + Cc + c] = hi;
            wdst[(size_t)oc * K3 + 2 * Cc + c] = lo;
        }
    }
}

// w'/x' pairing: w' = [wh|wh|wl], x' = [xh|xl|xh] => dot = wh.xh + wh.xl + wl.xh

// ===================== shared tile constants =====================
#define A_STRIDE 144
#define SA_BYTES (128*144)
#define STAGE_BYTES (2*SA_BYTES)
#define NSTAGE 3
#define GEMM_SMEM (NSTAGE*STAGE_BYTES)    // 110592
#define NKCHUNK 28

// ===================== launch 2: conv via split-bf16 tensor GEMM (templated copy) =====================
template<int KST>
DI void conv_load_chunk(uint32_t sbuf, const __nv_bfloat16* __restrict__ aptr,
                        const __nv_bfloat16* __restrict__ bptr, int k0, int t) {
    uint32_t sA = sbuf, sB = sbuf + SA_BYTES;
    #pragma unroll
    for (int i = 0; i < 4; i++) {
        int idx = t + i * 256;
        int row = idx >> 3, seg = idx & 7;
        cpasync16(sA + row * A_STRIDE + seg * 16, aptr + (size_t)row * KST + k0 + seg * 8);
    }
    #pragma unroll
    for (int i = 0; i < 4; i++) {
        int idx = t + i * 256;
        int row = idx >> 3, seg = idx & 7;
        cpasync16(sB + row * A_STRIDE + seg * 16, bptr + (size_t)row * KST + k0 + seg * 8);
    }
    cp_commit();
}

template<int CC, int WD>
DI void conv_tile(uint32_t sbase, const __nv_bfloat16* wp, const __nv_bfloat16* xp,
                  float* o, const float* wsrc, const float* bsrc,
                  int OC, int HW, int b, int oc0, int pp0, int t) {
    constexpr int K3 = 3 * CC;
    constexpr int nchunk = K3 / 64;
    int lane = t & 31, wid = t >> 5;
    int wm = wid & 1, wn = wid >> 1;
    float c[4][4][4];
    #pragma unroll
    for (int i = 0; i < 4; i++)
        #pragma unroll
        for (int j = 0; j < 4; j++)
            #pragma unroll
            for (int r = 0; r < 4; r++) c[i][j][r] = 0.f;
    const uint32_t a_row = wm * 64 + (lane & 15);
    const uint32_t a_base = a_row * A_STRIDE + ((lane >> 4) * 16);
    const uint32_t b_row = wn * 32 + ((lane >> 4) * 8) + (lane & 7);
    const uint32_t b_base = b_row * A_STRIDE + (((lane >> 3) & 1) * 16);

    const __nv_bfloat16* aptr = wp + (size_t)oc0 * K3;
    const __nv_bfloat16* bptr = xp + (size_t)(b * HW + pp0) * K3;
    conv_load_chunk<K3>(sbase, aptr, bptr, 0, t);
    conv_load_chunk<K3>(sbase + STAGE_BYTES, aptr, bptr, 64, t);
    int stage = 0;
    #pragma unroll 1
    for (int ck = 0; ck < nchunk; ck++) {
        if (ck == nchunk - 1) cp_wait0(); else cp_wait1();
        __syncthreads();
        if (ck + 2 < nchunk) {
            int ls = stage + 2; if (ls >= NSTAGE) ls -= NSTAGE;
            conv_load_chunk<K3>(sbase + ls * STAGE_BYTES, aptr, bptr, (ck + 2) * 64, t);
        }
        uint32_t sA = sbase + stage * STAGE_BYTES;
        uint32_t sB = sA + SA_BYTES;
        #pragma unroll
        for (int ks = 0; ks < 4; ks++) {
            uint32_t a[4][4];
            #pragma unroll
            for (int mi = 0; mi < 4; mi++)
                ldsm4(a[mi], sA + a_base + mi * (16 * A_STRIDE) + ks * 32);
            uint32_t bfr[2][4];
            #pragma unroll
            for (int np = 0; np < 2; np++)
                ldsm4(bfr[np], sB + b_base + np * (16 * A_STRIDE) + ks * 32);
            #pragma unroll
            for (int mi = 0; mi < 4; mi++)
                #pragma unroll
                for (int np = 0; np < 2; np++) {
                    mma16816(c[mi][np * 2 + 0], a[mi], bfr[np][0], bfr[np][1]);
                    mma16816(c[mi][np * 2 + 1], a[mi], bfr[np][2], bfr[np][3]);
                }
        }
        if (++stage >= NSTAGE) stage = 0;
    }

    constexpr int Cp2 = CC + 2;
    float invW = 2.f / (float)(WD - 1);
    #pragma unroll
    for (int mi = 0; mi < 4; mi++) {
        int r0 = oc0 + wm * 64 + mi * 16 + (lane >> 2);
        int r1 = r0 + 8;
        float cx0 = wsrc[(size_t)r0 * Cp2 + CC], cy0 = wsrc[(size_t)r0 * Cp2 + CC + 1], bb0 = bsrc[r0];
        float cx1 = wsrc[(size_t)r1 * Cp2 + CC], cy1 = wsrc[(size_t)r1 * Cp2 + CC + 1], bb1 = bsrc[r1];
        #pragma unroll
        for (int ni = 0; ni < 4; ni++) {
            int cc = pp0 + wn * 32 + ni * 8 + (lane & 3) * 2;
            float xga = -1.f + (float)(cc % WD) * invW, yga = -1.f + (float)(cc / WD) * invW;
            float xgb = -1.f + (float)((cc + 1) % WD) * invW, ygb = -1.f + (float)((cc + 1) / WD) * invW;
            float2 v0 = { c[mi][ni][0] + cx0 * xga + cy0 * yga + bb0,
                          c[mi][ni][1] + cx0 * xgb + cy0 * ygb + bb0 };
            float2 v1 = { c[mi][ni][2] + cx1 * xga + cy1 * yga + bb1,
                          c[mi][ni][3] + cx1 * xgb + cy1 * ygb + bb1 };
            *reinterpret_cast<float2*>(&o[(size_t)(b * OC + r0) * HW + cc]) = v0;
            *reinterpret_cast<float2*>(&o[(size_t)(b * OC + r1) * HW + cc]) = v1;
        }
    }
}

// grid 448: [0,64) L2 | [64,192) L1 | [192,448) L0
__global__ __launch_bounds__(256, 2) void convmma_kernel(
    const float* __restrict__ w1, const float* __restrict__ b1,
    const float* __restrict__ w2, const float* __restrict__ b2,
    const float* __restrict__ w3, const float* __restrict__ b3) {
    extern __shared__ __align__(16) char smem[];
    const uint32_t sbase = smem_u32(smem);
    int id = blockIdx.x, t = threadIdx.x;
    if (id < 64) {
        int b = id >> 4, rem = id & 15;
        conv_tile<1024, 16>(sbase, g_wp3, g_xp2, g_conv2, w3, b3,
                            1024, 256, b, (rem >> 1) * 128, (rem & 1) * 128, t);
    } else if (id < 192) {
        int v = id - 64;
        int b = v >> 5, rem = v & 31;
        conv_tile<512, 32>(sbase, g_wp2, g_xp1, g_conv1, w2, b2,
                           512, 1024, b, (rem >> 3) * 128, (rem & 7) * 128, t);
    } else {
        int v = id - 192;
        int b = v >> 6, rem = v & 63;
        conv_tile<256, 64>(sbase, g_wp1, g_xp0, g_conv0, w1, b1,
                           256, 4096, b, (rem >> 5) * 128, (rem & 31) * 128, t);
    }
}

// ===================== launch 3: phi (fused resize + out2 + feats) =====================
DI float bilin(const float* __restrict__ sp, int S, int p) {
    int h = p >> 6, ww = p & 63;
    float sc = (float)S / 64.f;
    float fy = ((float)h + 0.5f) * sc - 0.5f; fy = fminf(fmaxf(fy, 0.f), (float)(S - 1));
    float fx = ((float)ww + 0.5f) * sc - 0.5f; fx = fminf(fmaxf(fx, 0.f), (float)(S - 1));
    int y0 = (int)fy, x0 = (int)fx;
    int y1 = min(y0 + 1, S - 1), x1 = min(x0 + 1, S - 1);
    float wy = fy - (float)y0, wx = fx - (float)x0;
    float v00 = sp[y0 * S + x0], v01 = sp[y0 * S + x1];
    float v10 = sp[y1 * S + x0], v11 = sp[y1 * S + x1];
    return (1.f - wy) * ((1.f - wx) * v00 + wx * v01) + wy * ((1.f - wx) * v10 + wx * v11);
}

DI float fetch2(int b, int ch, int p) {
    if (ch < 256)  return g_conv0[(((size_t)(b * 256 + ch)) << 12) + p];
    if (ch < 768)  return bilin(&g_conv1[(size_t)(b * 512 + ch - 256) * 1024], 32, p);
    return bilin(&g_conv2[(size_t)(b * 1024 + ch - 768) * 256], 16, p);
}

__global__ __launch_bounds__(256) void phi_all_kernel(float* __restrict__ out2) {
    __shared__ float tile[32][33];
    __shared__ float fsmem[32];
    int b = blockIdx.y, p0 = blockIdx.x * 32;
    int tx = threadIdx.x & 31, ty = threadIdx.x >> 5;
    if (threadIdx.x < 32) fsmem[threadIdx.x] = 0.f;
    __syncthreads();
    #pragma unroll 1
    for (int ch0 = 0; ch0 < NCH; ch0 += 32) {
        for (int i = ty; i < 32; i += 8) {
            int ch = ch0 + i, p = p0 + tx;
            float v = fetch2(b, ch, p);
            tile[i][tx] = v;
            if (ch < 896)
                out2[(((size_t)(b * 896 + ch)) << 12) + p] = v;
        }
        __syncthreads();
        for (int i = ty; i < 32; i += 8) {
            int p = p0 + i;
            float v = tile[tx][i];
            g_phi[(size_t)(b * 4096 + p) * NCH + ch0 + tx] = __float2bfloat16(v);
            float s = v * v;
            s += __shfl_xor_sync(FULLMASK, s, 16);
            s += __shfl_xor_sync(FULLMASK, s, 8);
            s += __shfl_xor_sync(FULLMASK, s, 4);
            s += __shfl_xor_sync(FULLMASK, s, 2);
            s += __shfl_xor_sync(FULLMASK, s, 1);
            if (tx == 0) fsmem[i] += s;
        }
        __syncthreads();
    }
    if (threadIdx.x < 32)
        g_feats[b * 4096 + p0 + threadIdx.x] = fsmem[threadIdx.x];
}

// ===================== launch 4: distance GEMM (R12 code, verbatim) =====================
DI void gemm_load_chunk(uint32_t sbuf, int m0, int n0, int k0, int t) {
    uint32_t sA = sbuf, sB = sbuf + SA_BYTES;
    #pragma unroll
    for (int i = 0; i < 4; i++) {
        int idx = t + i * 256;
        int row = idx >> 3, seg = idx & 7;
        cpasync16(sA + row * A_STRIDE + seg * 16,
                  &g_phi[(size_t)(m0 + row) * NCH + k0 + seg * 8]);
    }
    #pragma unroll
    for (int i = 0; i < 4; i++) {
        int idx = t + i * 256;
        int row = idx >> 3, seg = idx & 7;
        cpasync16(sB + row * A_STRIDE + seg * 16,
                  &g_ct[(size_t)(n0 + row) * NCH + k0 + seg * 8]);
    }
    cp_commit();
}

__global__ __launch_bounds__(256, 2) void gemm_kernel() {
    extern __shared__ __align__(16) char smem[];
    const uint32_t sbase = smem_u32(smem);
    int t = threadIdx.x, lane = t & 31, wid = t >> 5;
    int wm = wid & 1, wn = wid >> 1;     // 2 x 4 warp grid; warp tile 64x32
    int m0 = blockIdx.x * 128, n0 = blockIdx.y * 128;

    float c[4][4][4];
    #pragma unroll
    for (int i = 0; i < 4; i++)
        #pragma unroll
        for (int j = 0; j < 4; j++)
            #pragma unroll
            for (int r = 0; r < 4; r++) c[i][j][r] = 0.f;

    const uint32_t a_row = wm * 64 + (lane & 15);
    const uint32_t a_base = a_row * A_STRIDE + ((lane >> 4) * 16);
    const uint32_t b_row = wn * 32 + ((lane >> 4) * 8) + (lane & 7);
    const uint32_t b_base = b_row * A_STRIDE + (((lane >> 3) & 1) * 16);

    gemm_load_chunk(sbase, m0, n0, 0, t);
    gemm_load_chunk(sbase + STAGE_BYTES, m0, n0, 64, t);

    int stage = 0;
    #pragma unroll 1
    for (int ck = 0; ck < NKCHUNK; ck++) {
        if (ck == NKCHUNK - 1) cp_wait0(); else cp_wait1();
        __syncthreads();
        if (ck + 2 < NKCHUNK) {
            int ls = stage + 2; if (ls >= NSTAGE) ls -= NSTAGE;
            gemm_load_chunk(sbase + ls * STAGE_BYTES, m0, n0, (ck + 2) * 64, t);
        }
        uint32_t sA = sbase + stage * STAGE_BYTES;
        uint32_t sB = sA + SA_BYTES;
        #pragma unroll
        for (int ks = 0; ks < 4; ks++) {
            uint32_t a[4][4];
            #pragma unroll
            for (int mi = 0; mi < 4; mi++)
                ldsm4(a[mi], sA + a_base + mi * (16 * A_STRIDE) + ks * 32);
            uint32_t bfr[2][4];
            #pragma unroll
            for (int np = 0; np < 2; np++)
                ldsm4(bfr[np], sB + b_base + np * (16 * A_STRIDE) + ks * 32);
            #pragma unroll
            for (int mi = 0; mi < 4; mi++)
                #pragma unroll
                for (int np = 0; np < 2; np++) {
                    mma16816(c[mi][np * 2 + 0], a[mi], bfr[np][0], bfr[np][1]);
                    mma16816(c[mi][np * 2 + 1], a[mi], bfr[np][2], bfr[np][3]);
                }
        }
        if (++stage >= NSTAGE) stage = 0;
    }

    // epilogue: store centered fp16 dist2 (dist2 - DCENTER)
    #pragma unroll
    for (int mi = 0; mi < 4; mi++) {
        int r0 = m0 + wm * 64 + mi * 16 + (lane >> 2);
        float f0 = g_feats[r0] - DCENTER, f1 = g_feats[r0 + 8] - DCENTER;
        #pragma unroll
        for (int ni = 0; ni < 4; ni++) {
            int cc = n0 + wn * 32 + ni * 8 + (lane & 3) * 2;
            float ce0 = g_cents[cc], ce1 = g_cents[cc + 1];
            __half* dp = &g_dist2h[(size_t)r0 * 4096 + cc];
            __half2 h0 = __floats2half2_rn(f0 + ce0 - 2.f * c[mi][ni][0],
                                           f0 + ce1 - 2.f * c[mi][ni][1]);
            __half2 h1 = __floats2half2_rn(f1 + ce0 - 2.f * c[mi][ni][2],
                                           f1 + ce1 - 2.f * c[mi][ni][3]);
            *reinterpret_cast<__half2*>(dp) = h0;
            *reinterpret_cast<__half2*>(dp + (size_t)8 * 4096) = h1;
        }
    }
}

// ===================== launch 5: top-200 per row (16-bit keys, 2 radix passes) =====================
DI unsigned order16(unsigned h) {
    return (h & 0x8000u) ? ((~h) & 0xFFFFu) : (h | 0x8000u);
}

__global__ __launch_bounds__(256) void topk_kernel(float* __restrict__ out) {
    __shared__ unsigned hist[256];
    __shared__ unsigned scan[256];
    __shared__ unsigned sh_want, sh_prefix;
    __shared__ unsigned cnt_lt;
    __shared__ int sel[256];

    int row = blockIdx.x;
    int t = threadIdx.x;
    int lane = t & 31;

    unsigned keys[16];
    const uint4* src = reinterpret_cast<const uint4*>(&g_dist2h[(size_t)row * 4096]);
    #pragma unroll
    for (int j = 0; j < 2; j++) {
        uint4 v = src[t + j * 256];
        unsigned ws[4] = { v.x, v.y, v.z, v.w };
        #pragma unroll
        for (int q = 0; q < 4; q++) {
            keys[j * 8 + q * 2 + 0] = order16(ws[q] & 0xFFFFu);
            keys[j * 8 + q * 2 + 1] = order16(ws[q] >> 16);
        }
    }
    if (t == 0) { sh_want = NNEI; sh_prefix = 0; cnt_lt = 0; }
    __syncthreads();

    // pass 0: high byte (clustered) -> warp-aggregated atomics
    {
        hist[t] = 0;
        __syncthreads();
        #pragma unroll
        for (int j = 0; j < 16; j++) {
            unsigned d = keys[j] >> 8;
            unsigned m = __match_any_sync(FULLMASK, d);
            if ((m & ((1u << lane) - 1u)) == 0)
                atomicAdd(&hist[d], (unsigned)__popc(m));
        }
        __syncthreads();
        if (t < 32) {
            unsigned vals[8], tot = 0;
            #pragma unroll
            for (int i = 0; i < 8; i++) { vals[i] = hist[t * 8 + i]; tot += vals[i]; }
            unsigned run = tot;
            #pragma unroll
            for (int off = 1; off < 32; off <<= 1) {
                unsigned x = __shfl_up_sync(FULLMASK, run, off);
                if (t >= off) run += x;
            }
            unsigned acc = run - tot;
            #pragma unroll
            for (int i = 0; i < 8; i++) { acc += vals[i]; scan[t * 8 + i] = acc; }
        }
        __syncthreads();
        unsigned below = (t == 0) ? 0u : scan[t - 1];
        if (below < NNEI && NNEI <= scan[t]) {
            sh_want = NNEI - below;
            sh_prefix = (unsigned)t;
        }
        __syncthreads();
    }

    // pass 1: low byte, plain atomics
    {
        unsigned pfx = sh_prefix;
        unsigned want = sh_want;
        hist[t] = 0;
        __syncthreads();
        #pragma unroll
        for (int j = 0; j < 16; j++) {
            unsigned u = keys[j];
            if ((u >> 8) == pfx)
                atomicAdd(&hist[u & 255u], 1u);
        }
        __syncthreads();
        if (t < 32) {
            unsigned vals[8], tot = 0;
            #pragma unroll
            for (int i = 0; i < 8; i++) { vals[i] = hist[t * 8 + i]; tot += vals[i]; }
            unsigned run = tot;
            #pragma unroll
            for (int off = 1; off < 32; off <<= 1) {
                unsigned x = __shfl_up_sync(FULLMASK, run, off);
                if (t >= off) run += x;
            }
            unsigned acc = run - tot;
            #pragma unroll
            for (int i = 0; i < 8; i++) { acc += vals[i]; scan[t * 8 + i] = acc; }
        }
        __syncthreads();
        unsigned below = (t == 0) ? 0u : scan[t - 1];
        if (below < want && want <= scan[t]) {
            sh_prefix = (pfx << 8) | (unsigned)t;
        }
        __syncthreads();
    }

    unsigned T = sh_prefix;
    #pragma unroll
    for (int j = 0; j < 16; j++) {
        bool pr = keys[j] < T;
        unsigned m = __ballot_sync(FULLMASK, pr);
        if (m) {
            unsigned pos0 = 0;
            if (lane == 0) pos0 = atomicAdd(&cnt_lt, (unsigned)__popc(m));
            pos0 = __shfl_sync(FULLMASK, pos0, 0);
            if (pr) sel[pos0 + __popc(m & ((1u << lane) - 1u))] = (int)keys[j];
        }
    }
    __syncthreads();
    unsigned base = cnt_lt;
    if ((unsigned)t >= base) sel[t] = (t < NNEI) ? (int)T : 0x7FFFFFFF;
    __syncthreads();

    for (int k = 2; k <= 256; k <<= 1) {
        for (int j = k >> 1; j > 0; j >>= 1) {
            int ixj = t ^ j;
            if (ixj > t) {
                bool up = ((t & k) == 0);
                int a = sel[t], bv = sel[ixj];
                if ((a > bv) == up) { sel[t] = bv; sel[ixj] = a; }
            }
            __syncthreads();
        }
    }

    if (t < NNEI) {
        unsigned u = (unsigned)sel[t];
        unsigned h = (u & 0x8000u) ? (u & 0x7FFFu) : ((~u) & 0xFFFFu);
        float f = __half2float(__ushort_as_half((unsigned short)h)) + DCENTER;
        int b = row >> 12, p = row & 4095;
        out[(((size_t)(b * NNEI + t)) << 12) + p] = sqrtf(f);
    }
}

// ===================== host launcher =====================
extern "C" void kernel_launch(void* const* d_in, const int* in_sizes, int n_in,
                              void* d_out, int out_size) {
    const float* p0 = (const float*)d_in[0];
    const float* p1 = (const float*)d_in[1];
    const float* p2 = (const float*)d_in[2];
    const float* w1 = (const float*)d_in[5];
    const float* b1 = (const float*)d_in[6];
    const float* w2 = (const float*)d_in[7];
    const float* b2 = (const float*)d_in[8];
    const float* w3 = (const float*)d_in[9];
    const float* b3 = (const float*)d_in[10];
    const float* Cm = (const float*)d_in[11];
    float* score = (float*)d_out;
    float* out2  = score + SCORE_ELEMS;

    static bool attr_set = false;
    if (!attr_set) {
        cudaFuncSetAttribute(gemm_kernel, cudaFuncAttributeMaxDynamicSharedMemorySize, GEMM_SMEM);
        cudaFuncSetAttribute(convmma_kernel, cudaFuncAttributeMaxDynamicSharedMemorySize, GEMM_SMEM);
        attr_set = true;
    }

    prep_kernel<<<16256, 256>>>(p0, p1, p2, Cm, w1, w2, w3);
    convmma_kernel<<<448, 256, GEMM_SMEM>>>(w1, b1, w2, b2, w3, b3);
    phi_all_kernel<<<dim3(128, 4), 256>>>(out2);
    gemm_kernel<<<dim3(M_TOT/128, NCENT/128), 256, GEMM_SMEM>>>();
    topk_kernel<<<M_TOT, 256>>>(score);
}